// round 8
// baseline (speedup 1.0000x reference)
#include <cuda_runtime.h>

#define DD 8
#define HH 64
#define TPB 256
#define RPC 256   // rows per CTA = TPB (1 row/thread)

// ---- dynamic shared memory layout (float offsets; all 16B aligned) ----
#define OW1T 0        // [9][64]   W1^T ([d][j], d==8 is t row)
#define OB1  576      // [64]
#define OW2T 640      // [64][64]  W2^T ([k][j]) forward
#define OW2  4736     // [64][64]  W2   ([j][k]) backward
#define OB2  8832     // [64]
#define OW3T 8896     // [64][8]   W3^T ([k][d])
#define OB3  9408     // [8] (+8 pad)
#define OW1S 9424     // [64] sum_{d<8} W1[k][d]
#define OW3S 9488     // [64] sum_d W3[d][j]
#define OH   9552     // [64][RPC] h1 state, col = tid
#define OG   25936    // [64][RPC] h2 / g_a2 state
#define SMEM_FLOATS 42320
#define SMEM_BYTES  (SMEM_FLOATS * 4)

typedef unsigned long long u64;
typedef ulonglong2 u64x2;

__device__ __forceinline__ u64 pk2(float a, float b) {
    u64 r; asm("mov.b64 %0, {%1,%2};" : "=l"(r) : "f"(a), "f"(b)); return r;
}
__device__ __forceinline__ void up2(u64 v, float& a, float& b) {
    asm("mov.b64 {%0,%1}, %2;" : "=f"(a), "=f"(b) : "l"(v));
}
__device__ __forceinline__ u64 f2fma(u64 a, u64 b, u64 c) {
    u64 d; asm("fma.rn.f32x2 %0, %1, %2, %3;" : "=l"(d) : "l"(a), "l"(b), "l"(c)); return d;
}
// tanh(x) = 1 - 2/(exp2(2*log2e*x)+1); saturates correctly, ~1e-6 rel err.
__device__ __forceinline__ float fast_tanh(float x) {
    float e; asm("ex2.approx.f32 %0, %1;" : "=f"(e) : "f"(x * 2.88539008177792681472f));
    float r; asm("rcp.approx.f32 %0, %1;" : "=f"(r) : "f"(e + 1.0f));
    return fmaf(-2.0f, r, 1.0f);
}

// 8 packed FMAs over a 16-wide weight row slice (4x LDS.128), broadcast p0.
// PW MUST be a (const u64*): +2 u64 = +16 bytes.
#define MAC16(PW) { \
    const u64x2 wA = *(const u64x2*)(PW); \
    const u64x2 wB = *(const u64x2*)((PW) + 2); \
    const u64x2 wC = *(const u64x2*)((PW) + 4); \
    const u64x2 wD = *(const u64x2*)((PW) + 6); \
    a0 = f2fma(p0, wA.x, a0); a1 = f2fma(p0, wA.y, a1); \
    a2 = f2fma(p0, wB.x, a2); a3 = f2fma(p0, wB.y, a3); \
    a4 = f2fma(p0, wC.x, a4); a5 = f2fma(p0, wC.y, a5); \
    a6 = f2fma(p0, wD.x, a6); a7 = f2fma(p0, wD.y, a7); }

// load 16 consecutive floats into 8 packed accumulators (u64-typed pointer!)
#define ACCLOAD16(PB) \
    const u64* _pb = (const u64*)(PB); \
    const u64x2 iA = *(const u64x2*)(_pb); \
    const u64x2 iB = *(const u64x2*)(_pb + 2); \
    const u64x2 iC = *(const u64x2*)(_pb + 4); \
    const u64x2 iD = *(const u64x2*)(_pb + 6); \
    u64 a0 = iA.x, a1 = iA.y, a2 = iB.x, a3 = iB.y; \
    u64 a4 = iC.x, a5 = iC.y, a6 = iD.x, a7 = iD.y;

// unpack 8 accums -> tanh -> 16 state stores at column tid
#define TSTORE16(OFF) \
    { float e, o; \
      up2(a0, e, o); dsm[(OFF)+(c+ 0)*RPC+tid] = fast_tanh(e); dsm[(OFF)+(c+ 1)*RPC+tid] = fast_tanh(o); \
      up2(a1, e, o); dsm[(OFF)+(c+ 2)*RPC+tid] = fast_tanh(e); dsm[(OFF)+(c+ 3)*RPC+tid] = fast_tanh(o); \
      up2(a2, e, o); dsm[(OFF)+(c+ 4)*RPC+tid] = fast_tanh(e); dsm[(OFF)+(c+ 5)*RPC+tid] = fast_tanh(o); \
      up2(a3, e, o); dsm[(OFF)+(c+ 6)*RPC+tid] = fast_tanh(e); dsm[(OFF)+(c+ 7)*RPC+tid] = fast_tanh(o); \
      up2(a4, e, o); dsm[(OFF)+(c+ 8)*RPC+tid] = fast_tanh(e); dsm[(OFF)+(c+ 9)*RPC+tid] = fast_tanh(o); \
      up2(a5, e, o); dsm[(OFF)+(c+10)*RPC+tid] = fast_tanh(e); dsm[(OFF)+(c+11)*RPC+tid] = fast_tanh(o); \
      up2(a6, e, o); dsm[(OFF)+(c+12)*RPC+tid] = fast_tanh(e); dsm[(OFF)+(c+13)*RPC+tid] = fast_tanh(o); \
      up2(a7, e, o); dsm[(OFF)+(c+14)*RPC+tid] = fast_tanh(e); dsm[(OFF)+(c+15)*RPC+tid] = fast_tanh(o); }

__global__ void __launch_bounds__(TPB, 1)
cnf_kernel(const float* __restrict__ x0,
           const float* __restrict__ W1g,   // [64][9]
           const float* __restrict__ b1g,   // [64]
           const float* __restrict__ W2g,   // [64][64]
           const float* __restrict__ b2g,   // [64]
           const float* __restrict__ W3g,   // [8][64]
           const float* __restrict__ b3g,   // [8]
           const int*   __restrict__ nsp,
           float* __restrict__ out, int n)
{
    extern __shared__ float dsm[];
    const int tid = threadIdx.x;

    // ---------------- cooperative weight init ----------------
    for (int idx = tid; idx < HH * HH; idx += TPB) {
        int j = idx >> 6, k = idx & 63;
        float v = W2g[idx];
        dsm[OW2 + j * HH + k]  = v;   // [j][k]
        dsm[OW2T + k * HH + j] = v;   // [k][j]
    }
    for (int idx = tid; idx < HH * (DD + 1); idx += TPB) {
        int j = idx / (DD + 1), d = idx % (DD + 1);
        dsm[OW1T + d * HH + j] = W1g[idx];
    }
    for (int idx = tid; idx < HH * DD; idx += TPB) {
        int d = idx >> 6, k = idx & 63;
        dsm[OW3T + k * DD + d] = W3g[idx];
    }
    for (int idx = tid; idx < HH; idx += TPB) {
        dsm[OB1 + idx] = b1g[idx];
        dsm[OB2 + idx] = b2g[idx];
        float s1 = 0.f;
        for (int d = 0; d < DD; d++) s1 += W1g[idx * (DD + 1) + d];
        dsm[OW1S + idx] = s1;
        float s3 = 0.f;
        for (int d = 0; d < DD; d++) s3 += W3g[d * HH + idx];
        dsm[OW3S + idx] = s3;
    }
    if (tid < DD) dsm[OB3 + tid] = b3g[tid];
    __syncthreads();

    const int row = blockIdx.x * RPC + tid;
    const bool act = row < n;
    const int lrow = act ? row : 0;

    float x0r, x1r, x2r, x3r, x4r, x5r, x6r, x7r;
    {
        float4 v0 = ((const float4*)x0)[lrow * 2];
        float4 v1 = ((const float4*)x0)[lrow * 2 + 1];
        x0r = v0.x; x1r = v0.y; x2r = v0.z; x3r = v0.w;
        x4r = v1.x; x5r = v1.y; x6r = v1.z; x7r = v1.w;
    }
    float ld = 0.f;

    const int nsteps = nsp ? *nsp : 100;
    const float dt = 1.0f / (float)nsteps;

    #pragma unroll 1
    for (int i = 0; i < nsteps; i++) {
        const float t = (float)i * dt;

        #pragma unroll 1
        for (int pass = 0; pass < 2; pass++) {
            // ---- layer 1: OH = tanh(W1 @ [x; t] + b1) ----
            #pragma unroll 1
            for (int c = 0; c < HH; c += 16) {
                ACCLOAD16(&dsm[OB1 + c])
                #define L1ROW(d, s) { \
                    const u64 p0 = pk2(s, s); \
                    MAC16((const u64*)&dsm[OW1T + (d) * HH + c]) }
                L1ROW(0, x0r) L1ROW(1, x1r) L1ROW(2, x2r) L1ROW(3, x3r)
                L1ROW(4, x4r) L1ROW(5, x5r) L1ROW(6, x6r) L1ROW(7, x7r)
                L1ROW(8, t)
                #undef L1ROW
                TSTORE16(OH)
            }
            // ---- layer 2: OG = tanh(W2 @ h + b2) ----
            #pragma unroll 1
            for (int c = 0; c < HH; c += 16) {
                ACCLOAD16(&dsm[OB2 + c])
                #pragma unroll 8
                for (int k = 0; k < HH; k++) {
                    const float s = dsm[OH + k * RPC + tid];
                    const u64 p0 = pk2(s, s);
                    MAC16((const u64*)&dsm[OW2T + k * HH + c])
                }
                TSTORE16(OG)
            }
            // ---- layer 3 (pass 0 only): x += dt * (W3 @ h2 + b3) ----
            if (pass == 0) {
                const u64x2 iA = *(const u64x2*)&dsm[OB3];
                const u64x2 iB = *(const u64x2*)&dsm[OB3 + 4];
                u64 a0 = iA.x, a1 = iA.y, a2 = iB.x, a3 = iB.y;
                #pragma unroll 8
                for (int k = 0; k < HH; k++) {
                    const float s = dsm[OG + k * RPC + tid];
                    const u64 p0 = pk2(s, s);
                    const u64x2 wA = *(const u64x2*)&dsm[OW3T + k * DD];
                    const u64x2 wB = *(const u64x2*)&dsm[OW3T + k * DD + 4];
                    a0 = f2fma(p0, wA.x, a0); a1 = f2fma(p0, wA.y, a1);
                    a2 = f2fma(p0, wB.x, a2); a3 = f2fma(p0, wB.y, a3);
                }
                float e, o;
                up2(a0, e, o); x0r = fmaf(dt, e, x0r); x1r = fmaf(dt, o, x1r);
                up2(a1, e, o); x2r = fmaf(dt, e, x2r); x3r = fmaf(dt, o, x3r);
                up2(a2, e, o); x4r = fmaf(dt, e, x4r); x5r = fmaf(dt, o, x5r);
                up2(a3, e, o); x6r = fmaf(dt, e, x6r); x7r = fmaf(dt, o, x7r);
            }
        }

        // ---------------- backward (VJP, ones cotangent) ----------------
        // OG[j] := w3s[j] * (1 - h2[j]^2)
        #pragma unroll 8
        for (int j = 0; j < HH; j++) {
            const float w = dsm[OW3S + j];
            const float g = dsm[OG + j * RPC + tid];
            dsm[OG + j * RPC + tid] = fmaf(-(g * w), g, w);
        }
        // gh1[k] = sum_j g_a2[j] * W2[j][k]; fold tanh' and w1s into ld
        float s0 = 0.f, s1 = 0.f;
        #pragma unroll 1
        for (int c = 0; c < HH; c += 16) {
            u64 a0 = 0ull, a1 = 0ull, a2 = 0ull, a3 = 0ull;
            u64 a4 = 0ull, a5 = 0ull, a6 = 0ull, a7 = 0ull;
            #pragma unroll 8
            for (int j = 0; j < HH; j++) {
                const float s = dsm[OG + j * RPC + tid];
                const u64 p0 = pk2(s, s);
                MAC16((const u64*)&dsm[OW2 + j * HH + c])
            }
            #define LDFOLD(ACC, K0) { \
                float e, o; up2(ACC, e, o); \
                { float hh = dsm[OH + (K0) * RPC + tid]; \
                  float tt = e * dsm[OW1S + (K0)]; \
                  s0 += tt; s0 = fmaf(-(tt * hh), hh, s0); } \
                { float hh = dsm[OH + ((K0) + 1) * RPC + tid]; \
                  float tt = o * dsm[OW1S + (K0) + 1]; \
                  s1 += tt; s1 = fmaf(-(tt * hh), hh, s1); } }
            LDFOLD(a0, c + 0)  LDFOLD(a1, c + 2)
            LDFOLD(a2, c + 4)  LDFOLD(a3, c + 6)
            LDFOLD(a4, c + 8)  LDFOLD(a5, c + 10)
            LDFOLD(a6, c + 12) LDFOLD(a7, c + 14)
            #undef LDFOLD
        }
        ld = fmaf(dt, s0 + s1, ld);
    }

    if (act) {
        float4 v0, v1;
        v0.x = x0r; v0.y = x1r; v0.z = x2r; v0.w = x3r;
        v1.x = x4r; v1.y = x5r; v1.z = x6r; v1.w = x7r;
        ((float4*)out)[row * 2]     = v0;
        ((float4*)out)[row * 2 + 1] = v1;
        out[n * DD + row] = ld;
    }
}

extern "C" void kernel_launch(void* const* d_in, const int* in_sizes, int n_in,
                              void* d_out, int out_size) {
    const float* x0 = (const float*)d_in[0];
    const float* W1 = (const float*)d_in[1];
    const float* b1 = (const float*)d_in[2];
    const float* W2 = (const float*)d_in[3];
    const float* b2 = (const float*)d_in[4];
    const float* W3 = (const float*)d_in[5];
    const float* b3 = (const float*)d_in[6];
    const int* nsp = (n_in > 7) ? (const int*)d_in[7] : nullptr;

    cudaFuncSetAttribute(cnf_kernel,
                         cudaFuncAttributeMaxDynamicSharedMemorySize, SMEM_BYTES);

    int n = in_sizes[0] / DD;
    int blocks = (n + RPC - 1) / RPC;
    cnf_kernel<<<blocks, TPB, SMEM_BYTES>>>(x0, W1, b1, W2, b2, W3, b3, nsp,
                                            (float*)d_out, n);
}